// round 2
// baseline (speedup 1.0000x reference)
#include <cuda_runtime.h>

// Problem constants
#define T_LEN 1024
#define B_SZ 2
#define E_DIM 1024
#define H_NUM 16
#define D_DIM 64
#define TB (T_LEN * B_SZ)          // 2048
#define CH 128                     // chunk length
#define NC (T_LEN / CH)            // 8 chunks
#define BHN (B_SZ * H_NUM)         // 32 head-batches
#define SCALE_ATT 0.125f           // 1/sqrt(64)

typedef unsigned long long ull;

// Scratch (device globals; no allocation allowed)
__device__ float g_q[BHN * T_LEN * D_DIM];     // (b,h,t,d)
__device__ float g_k[BHN * T_LEN * D_DIM];
__device__ float g_v[BHN * T_LEN * D_DIM];
__device__ float g_attn[TB * E_DIM];           // (t,b,e)
__device__ float g_kvc[BHN * NC * D_DIM * D_DIM];   // per-chunk K^T V
__device__ float g_ssum[BHN * NC * D_DIM * D_DIM];  // exclusive prefix

// ---- packed f32x2 helpers ---------------------------------------------------
__device__ __forceinline__ void fma2(ull& d, ull a, ull b) {
    asm("fma.rn.f32x2 %0, %1, %2, %0;" : "+l"(d) : "l"(a), "l"(b));
}
__device__ __forceinline__ ull dup2(float x) {
    ull r; asm("mov.b64 %0, {%1, %1};" : "=l"(r) : "f"(x)); return r;
}
__device__ __forceinline__ float2 unpk(ull v) {
    float2 r; asm("mov.b64 {%0, %1}, %2;" : "=f"(r.x), "=f"(r.y) : "l"(v)); return r;
}

// ---------------------------------------------------------------------------
// Input projection: for z in {q,k,v}:  out = X @ W_z^T + b_z, scattered into
// (b,h,t,d) layout. 128x128x8 SGEMM with f32x2 packed FMA, A tile stored
// duplicated in smem so the broadcast operand needs no pack instructions.
// ---------------------------------------------------------------------------
__global__ __launch_bounds__(256, 2) void inproj_kernel(
    const float* __restrict__ q_in, const float* __restrict__ k_in,
    const float* __restrict__ v_in, const float* __restrict__ W,
    const float* __restrict__ bias)
{
    __shared__ float As[8][256];   // duplicated pairs: (a,a) per row
    __shared__ float Bs[8][128];

    const int z = blockIdx.z;
    const float* A  = (z == 0) ? q_in : ((z == 1) ? k_in : v_in);
    const float* Wz = W + z * E_DIM * E_DIM;
    const float* bz = bias + z * E_DIM;

    const int tid = threadIdx.x;
    const int tx = tid & 15, ty = tid >> 4;
    const int m0 = blockIdx.y * 128, n0 = blockIdx.x * 128;
    const int lrow = tid >> 1;
    const int lk4  = (tid & 1) << 2;

    const float* Aptr = A  + (m0 + lrow) * E_DIM + lk4;
    const float* Bptr = Wz + (n0 + lrow) * E_DIM + lk4;

    ull acc[8][4];
    #pragma unroll
    for (int i = 0; i < 8; ++i)
        #pragma unroll
        for (int j = 0; j < 4; ++j) acc[i][j] = 0ull;

    float4 a4 = *(const float4*)(Aptr);
    float4 b4 = *(const float4*)(Bptr);

    for (int k0 = 0; k0 < E_DIM; k0 += 8) {
        __syncthreads();
        ((ull*)&As[lk4 + 0][0])[lrow] = dup2(a4.x);
        ((ull*)&As[lk4 + 1][0])[lrow] = dup2(a4.y);
        ((ull*)&As[lk4 + 2][0])[lrow] = dup2(a4.z);
        ((ull*)&As[lk4 + 3][0])[lrow] = dup2(a4.w);
        Bs[lk4 + 0][lrow] = b4.x; Bs[lk4 + 1][lrow] = b4.y;
        Bs[lk4 + 2][lrow] = b4.z; Bs[lk4 + 3][lrow] = b4.w;
        __syncthreads();
        if (k0 + 8 < E_DIM) {
            a4 = *(const float4*)(Aptr + k0 + 8);
            b4 = *(const float4*)(Bptr + k0 + 8);
        }
        #pragma unroll
        for (int kk = 0; kk < 8; ++kk) {
            const ulonglong2* Ap = (const ulonglong2*)&As[kk][ty * 16];
            ulonglong2 ad0 = Ap[0], ad1 = Ap[1], ad2 = Ap[2], ad3 = Ap[3];
            const ulonglong2* Bp = (const ulonglong2*)&Bs[kk][tx * 8];
            ulonglong2 bd0 = Bp[0], bd1 = Bp[1];
            ull av[8] = {ad0.x, ad0.y, ad1.x, ad1.y, ad2.x, ad2.y, ad3.x, ad3.y};
            ull bv[4] = {bd0.x, bd0.y, bd1.x, bd1.y};
            #pragma unroll
            for (int i = 0; i < 8; ++i)
                #pragma unroll
                for (int j = 0; j < 4; ++j)
                    fma2(acc[i][j], av[i], bv[j]);
        }
    }

    float* outb = (z == 0) ? g_q : ((z == 1) ? g_k : g_v);
    #pragma unroll
    for (int i = 0; i < 8; ++i) {
        const int m = m0 + ty * 8 + i;
        const int t = m >> 1, b = m & 1;
        #pragma unroll
        for (int j = 0; j < 4; ++j) {
            const int n = n0 + tx * 8 + 2 * j;
            const int h = n >> 6, d = n & 63;
            float2 r = unpk(acc[i][j]);
            float* dst = &outb[((b * H_NUM + h) * T_LEN + t) * D_DIM + d];
            dst[0] = r.x + bz[n];
            dst[1] = r.y + bz[n + 1];
        }
    }
}

// ---------------------------------------------------------------------------
// Output projection: out = attn @ Wo^T + bo. Same packed-SGEMM structure.
// ---------------------------------------------------------------------------
__global__ __launch_bounds__(256, 2) void outproj_kernel(
    const float* __restrict__ W, const float* __restrict__ bias,
    float* __restrict__ out)
{
    __shared__ float As[8][256];
    __shared__ float Bs[8][128];

    const int tid = threadIdx.x;
    const int tx = tid & 15, ty = tid >> 4;
    const int m0 = blockIdx.y * 128, n0 = blockIdx.x * 128;
    const int lrow = tid >> 1;
    const int lk4  = (tid & 1) << 2;

    const float* Aptr = g_attn + (m0 + lrow) * E_DIM + lk4;
    const float* Bptr = W      + (n0 + lrow) * E_DIM + lk4;

    ull acc[8][4];
    #pragma unroll
    for (int i = 0; i < 8; ++i)
        #pragma unroll
        for (int j = 0; j < 4; ++j) acc[i][j] = 0ull;

    float4 a4 = *(const float4*)(Aptr);
    float4 b4 = *(const float4*)(Bptr);

    for (int k0 = 0; k0 < E_DIM; k0 += 8) {
        __syncthreads();
        ((ull*)&As[lk4 + 0][0])[lrow] = dup2(a4.x);
        ((ull*)&As[lk4 + 1][0])[lrow] = dup2(a4.y);
        ((ull*)&As[lk4 + 2][0])[lrow] = dup2(a4.z);
        ((ull*)&As[lk4 + 3][0])[lrow] = dup2(a4.w);
        Bs[lk4 + 0][lrow] = b4.x; Bs[lk4 + 1][lrow] = b4.y;
        Bs[lk4 + 2][lrow] = b4.z; Bs[lk4 + 3][lrow] = b4.w;
        __syncthreads();
        if (k0 + 8 < E_DIM) {
            a4 = *(const float4*)(Aptr + k0 + 8);
            b4 = *(const float4*)(Bptr + k0 + 8);
        }
        #pragma unroll
        for (int kk = 0; kk < 8; ++kk) {
            const ulonglong2* Ap = (const ulonglong2*)&As[kk][ty * 16];
            ulonglong2 ad0 = Ap[0], ad1 = Ap[1], ad2 = Ap[2], ad3 = Ap[3];
            const ulonglong2* Bp = (const ulonglong2*)&Bs[kk][tx * 8];
            ulonglong2 bd0 = Bp[0], bd1 = Bp[1];
            ull av[8] = {ad0.x, ad0.y, ad1.x, ad1.y, ad2.x, ad2.y, ad3.x, ad3.y};
            ull bv[4] = {bd0.x, bd0.y, bd1.x, bd1.y};
            #pragma unroll
            for (int i = 0; i < 8; ++i)
                #pragma unroll
                for (int j = 0; j < 4; ++j)
                    fma2(acc[i][j], av[i], bv[j]);
        }
    }

    #pragma unroll
    for (int i = 0; i < 8; ++i) {
        const int m = m0 + ty * 8 + i;
        #pragma unroll
        for (int j = 0; j < 4; ++j) {
            const int n = n0 + tx * 8 + 2 * j;
            float2 r = unpk(acc[i][j]);
            out[m * E_DIM + n]     = r.x + bias[n];
            out[m * E_DIM + n + 1] = r.y + bias[n + 1];
        }
    }
}

// ---------------------------------------------------------------------------
// Pass A: per (head, chunk) compute KV_c = K_c^T V_c  (64x64, depth 128)
// ---------------------------------------------------------------------------
__global__ __launch_bounds__(256) void kvchunk_kernel()
{
    const int c = blockIdx.x, bh = blockIdx.y;
    const float* Kg = g_k + (bh * T_LEN + c * CH) * D_DIM;
    const float* Vg = g_v + (bh * T_LEN + c * CH) * D_DIM;
    __shared__ float Ks[32 * 64];
    __shared__ float Vs[32 * 64];
    const int tid = threadIdx.x;
    const int tx = tid & 15, ty = tid >> 4;

    ull acc[4][2];
    #pragma unroll
    for (int i = 0; i < 4; ++i) { acc[i][0] = 0ull; acc[i][1] = 0ull; }

    for (int s0 = 0; s0 < CH; s0 += 32) {
        __syncthreads();
        #pragma unroll
        for (int u = 0; u < 2; ++u) {
            const int idx = tid * 4 + u * 1024;
            *(float4*)&Ks[idx] = *(const float4*)&Kg[s0 * 64 + idx];
            *(float4*)&Vs[idx] = *(const float4*)&Vg[s0 * 64 + idx];
        }
        __syncthreads();
        #pragma unroll 8
        for (int ss = 0; ss < 32; ++ss) {
            float4 kq = *(const float4*)&Ks[ss * 64 + ty * 4];
            ulonglong2 vv = *(const ulonglong2*)&Vs[ss * 64 + tx * 4];
            ull kd[4] = {dup2(kq.x), dup2(kq.y), dup2(kq.z), dup2(kq.w)};
            #pragma unroll
            for (int i = 0; i < 4; ++i) {
                fma2(acc[i][0], kd[i], vv.x);
                fma2(acc[i][1], kd[i], vv.y);
            }
        }
    }

    float* outp = g_kvc + (bh * NC + c) * D_DIM * D_DIM;
    #pragma unroll
    for (int i = 0; i < 4; ++i) {
        float2 r0 = unpk(acc[i][0]);
        float2 r1 = unpk(acc[i][1]);
        float* dst = &outp[(ty * 4 + i) * 64 + tx * 4];
        dst[0] = r0.x; dst[1] = r0.y; dst[2] = r1.x; dst[3] = r1.y;
    }
}

// ---------------------------------------------------------------------------
// Pass B: exclusive prefix-sum of chunk KV states over the 8 chunks
// ---------------------------------------------------------------------------
__global__ __launch_bounds__(256) void scan_kernel()
{
    const int bh = blockIdx.x;
    for (int e = threadIdx.x; e < D_DIM * D_DIM; e += 256) {
        float s = 0.f;
        #pragma unroll
        for (int c = 0; c < NC; ++c) {
            g_ssum[(bh * NC + c) * D_DIM * D_DIM + e] = s;
            s += g_kvc[(bh * NC + c) * D_DIM * D_DIM + e];
        }
    }
}

// ---------------------------------------------------------------------------
// Pass C: per (head, chunk): O_c = (Q_c @ S_c + tril(Q_c K_c^T) @ V_c) * scale
// smem: Q(128x65), K(128x65), V(128x64), S(64x64), P(128x128) = 177 KB
// ---------------------------------------------------------------------------
#define SMEM_C_FLOATS (128 * 65 + 128 * 65 + 128 * 64 + 64 * 64 + 128 * 128)
#define SMEM_C_BYTES (SMEM_C_FLOATS * 4)

__global__ __launch_bounds__(256) void attn_kernel()
{
    extern __shared__ float sm[];
    float* Qs = sm;                    // 128 x 65 (padded)
    float* Ks = Qs + 128 * 65;         // 128 x 65 (padded)
    float* Vs = Ks + 128 * 65;         // 128 x 64
    float* Ss = Vs + 128 * 64;         // 64 x 64
    float* Ps = Ss + 64 * 64;          // 128 x 128

    const int c = blockIdx.x, bh = blockIdx.y;
    const int tid = threadIdx.x;
    const float* Qg = g_q + (bh * T_LEN + c * CH) * D_DIM;
    const float* Kg = g_k + (bh * T_LEN + c * CH) * D_DIM;
    const float* Vg = g_v + (bh * T_LEN + c * CH) * D_DIM;
    const float* Sg = g_ssum + (bh * NC + c) * D_DIM * D_DIM;

    // Load tiles
    for (int idx = tid * 4; idx < CH * D_DIM; idx += 256 * 4) {
        const int row = idx >> 6, col = idx & 63;
        float4 q4 = *(const float4*)&Qg[idx];
        float4 k4 = *(const float4*)&Kg[idx];
        *(float4*)&Vs[idx] = *(const float4*)&Vg[idx];
        Qs[row * 65 + col + 0] = q4.x; Qs[row * 65 + col + 1] = q4.y;
        Qs[row * 65 + col + 2] = q4.z; Qs[row * 65 + col + 3] = q4.w;
        Ks[row * 65 + col + 0] = k4.x; Ks[row * 65 + col + 1] = k4.y;
        Ks[row * 65 + col + 2] = k4.z; Ks[row * 65 + col + 3] = k4.w;
    }
    for (int idx = tid * 4; idx < D_DIM * D_DIM; idx += 256 * 4)
        *(float4*)&Ss[idx] = *(const float4*)&Sg[idx];
    __syncthreads();

    const int tx = tid & 15, ty = tid >> 4;

    // P = tril(Q K^T), 128x128, 64 per-thread outputs (8x8)
    {
        float p[8][8];
        #pragma unroll
        for (int i = 0; i < 8; ++i)
            #pragma unroll
            for (int j = 0; j < 8; ++j) p[i][j] = 0.f;

        #pragma unroll 4
        for (int d = 0; d < D_DIM; ++d) {
            float qf[8], kf[8];
            #pragma unroll
            for (int i = 0; i < 8; ++i) qf[i] = Qs[(ty * 8 + i) * 65 + d];
            #pragma unroll
            for (int j = 0; j < 8; ++j) kf[j] = Ks[(tx * 8 + j) * 65 + d];
            #pragma unroll
            for (int i = 0; i < 8; ++i)
                #pragma unroll
                for (int j = 0; j < 8; ++j)
                    p[i][j] = fmaf(qf[i], kf[j], p[i][j]);
        }
        #pragma unroll
        for (int i = 0; i < 8; ++i) {
            const int i_ = ty * 8 + i;
            #pragma unroll
            for (int j = 0; j < 8; ++j) {
                const int j_ = tx * 8 + j;
                Ps[i_ * 128 + j_] = (j_ <= i_) ? p[i][j] : 0.f;
            }
        }
    }
    __syncthreads();

    // O = Q @ S + P @ V, 128x64, per-thread 8 rows x 2 col-pairs (f32x2)
    {
        const int v0 = tx * 4;
        const int i0 = ty * 8;
        ull o[8][2];
        #pragma unroll
        for (int i = 0; i < 8; ++i) { o[i][0] = 0ull; o[i][1] = 0ull; }

        #pragma unroll 4
        for (int k = 0; k < D_DIM; ++k) {
            ulonglong2 sp = *(const ulonglong2*)&Ss[k * 64 + v0];
            #pragma unroll
            for (int i = 0; i < 8; ++i) {
                ull qd = dup2(Qs[(i0 + i) * 65 + k]);
                fma2(o[i][0], qd, sp.x);
                fma2(o[i][1], qd, sp.y);
            }
        }
        #pragma unroll 4
        for (int j2 = 0; j2 < CH; ++j2) {
            ulonglong2 vp = *(const ulonglong2*)&Vs[j2 * 64 + v0];
            #pragma unroll
            for (int i = 0; i < 8; ++i) {
                ull pd = dup2(Ps[(i0 + i) * 128 + j2]);
                fma2(o[i][0], pd, vp.x);
                fma2(o[i][1], pd, vp.y);
            }
        }

        const int b = bh / H_NUM, h = bh % H_NUM;
        #pragma unroll
        for (int i = 0; i < 8; ++i) {
            const int t = c * CH + i0 + i;
            float* dst = g_attn + (t * B_SZ + b) * E_DIM + h * D_DIM + v0;
            float2 r0 = unpk(o[i][0]);
            float2 r1 = unpk(o[i][1]);
            dst[0] = r0.x * SCALE_ATT; dst[1] = r0.y * SCALE_ATT;
            dst[2] = r1.x * SCALE_ATT; dst[3] = r1.y * SCALE_ATT;
        }
    }
}

// ---------------------------------------------------------------------------
extern "C" void kernel_launch(void* const* d_in, const int* in_sizes, int n_in,
                              void* d_out, int out_size)
{
    (void)in_sizes; (void)n_in; (void)out_size;
    const float* query = (const float*)d_in[0];
    const float* key_  = (const float*)d_in[1];
    const float* value = (const float*)d_in[2];
    const float* ipw   = (const float*)d_in[3];
    const float* ipb   = (const float*)d_in[4];
    const float* opw   = (const float*)d_in[5];
    const float* opb   = (const float*)d_in[6];
    float* out = (float*)d_out;

    cudaFuncSetAttribute(attn_kernel,
                         cudaFuncAttributeMaxDynamicSharedMemorySize,
                         SMEM_C_BYTES);

    dim3 g1(E_DIM / 128, TB / 128, 3);
    inproj_kernel<<<g1, 256>>>(query, key_, value, ipw, ipb);

    kvchunk_kernel<<<dim3(NC, BHN), 256>>>();
    scan_kernel<<<BHN, 256>>>();
    attn_kernel<<<dim3(NC, BHN), 256, SMEM_C_BYTES>>>();

    dim3 g2(E_DIM / 128, TB / 128);
    outproj_kernel<<<g2, 256>>>(opw, opb, out);
}

// round 4
// speedup vs baseline: 2.1251x; 2.1251x over previous
#include <cuda_runtime.h>
#include <cuda_bf16.h>
#include <cstdint>

// Problem constants
#define T_LEN 1024
#define B_SZ 2
#define E_DIM 1024
#define H_NUM 16
#define D_DIM 64
#define TB (T_LEN * B_SZ)          // 2048
#define CH 128                     // chunk length
#define NC (T_LEN / CH)            // 8 chunks
#define BHN (B_SZ * H_NUM)         // 32 head-batches
#define SCALE_ATT 0.125f           // 1/sqrt(64)

typedef unsigned long long ull;
typedef __nv_bfloat16 bf16;

// Scratch (device globals; no allocation allowed)
__device__ float g_q[BHN * T_LEN * D_DIM];
__device__ float g_k[BHN * T_LEN * D_DIM];
__device__ float g_v[BHN * T_LEN * D_DIM];
__device__ float g_attn[TB * E_DIM];
__device__ float g_kvc[BHN * NC * D_DIM * D_DIM];
__device__ float g_ssum[BHN * NC * D_DIM * D_DIM];

// bf16 hi/lo planes for tensor-core GEMMs
__device__ __align__(16) bf16 g_xh[3 * TB * E_DIM];
__device__ __align__(16) bf16 g_xl[3 * TB * E_DIM];
__device__ __align__(16) bf16 g_wh[4 * E_DIM * E_DIM];
__device__ __align__(16) bf16 g_wl[4 * E_DIM * E_DIM];
__device__ __align__(16) bf16 g_ah[TB * E_DIM];
__device__ __align__(16) bf16 g_al[TB * E_DIM];

// ---- packed f32x2 helpers (attention kernels) -------------------------------
__device__ __forceinline__ void fma2(ull& d, ull a, ull b) {
    asm("fma.rn.f32x2 %0, %1, %2, %0;" : "+l"(d) : "l"(a), "l"(b));
}
__device__ __forceinline__ ull dup2(float x) {
    ull r; asm("mov.b64 %0, {%1, %1};" : "=l"(r) : "f"(x)); return r;
}
__device__ __forceinline__ float2 unpk(ull v) {
    float2 r; asm("mov.b64 {%0, %1}, %2;" : "=f"(r.x), "=f"(r.y) : "l"(v)); return r;
}

// ---- mma.sync helpers --------------------------------------------------------
__device__ __forceinline__ uint32_t smem_u32(const void* p) {
    uint32_t a;
    asm("{ .reg .u64 t; cvta.to.shared.u64 t, %1; cvt.u32.u64 %0, t; }"
        : "=r"(a) : "l"(p));
    return a;
}
__device__ __forceinline__ void cp16(uint32_t dst, const void* src) {
    asm volatile("cp.async.ca.shared.global [%0], [%1], 16;"
                 :: "r"(dst), "l"(src) : "memory");
}
#define CP_COMMIT() asm volatile("cp.async.commit_group;" ::: "memory")
#define CP_WAIT(n)  asm volatile("cp.async.wait_group %0;" :: "n"(n) : "memory")

__device__ __forceinline__ void ldm_x4(uint32_t* r, uint32_t addr) {
    asm volatile("ldmatrix.sync.aligned.m8n8.x4.shared.b16 {%0,%1,%2,%3}, [%4];"
                 : "=r"(r[0]), "=r"(r[1]), "=r"(r[2]), "=r"(r[3]) : "r"(addr));
}
__device__ __forceinline__ void ldm_x2(uint32_t* r, uint32_t addr) {
    asm volatile("ldmatrix.sync.aligned.m8n8.x2.shared.b16 {%0,%1}, [%2];"
                 : "=r"(r[0]), "=r"(r[1]) : "r"(addr));
}
__device__ __forceinline__ void mma_bf16(float* c, const uint32_t* a, const uint32_t* b) {
    asm volatile(
        "mma.sync.aligned.m16n8k16.row.col.f32.bf16.bf16.f32 "
        "{%0,%1,%2,%3}, {%4,%5,%6,%7}, {%8,%9}, {%0,%1,%2,%3};"
        : "+f"(c[0]), "+f"(c[1]), "+f"(c[2]), "+f"(c[3])
        : "r"(a[0]), "r"(a[1]), "r"(a[2]), "r"(a[3]), "r"(b[0]), "r"(b[1]));
}

// ---------------------------------------------------------------------------
// Split: fp32 -> (hi, lo) bf16 planes.  sel: 0=g_x*, 1=g_w*, 2=g_a* (src=g_attn)
// ---------------------------------------------------------------------------
__global__ __launch_bounds__(256) void split_kernel(
    const float* __restrict__ src, int sel, int off, int n4)
{
    const int i = blockIdx.x * 256 + threadIdx.x;
    if (i >= n4) return;
    bf16* hi; bf16* lo;
    const float* s = src;
    if (sel == 0)      { hi = g_xh; lo = g_xl; }
    else if (sel == 1) { hi = g_wh; lo = g_wl; }
    else               { hi = g_ah; lo = g_al; s = g_attn; }
    hi += off; lo += off;

    float4 v = ((const float4*)s)[i];
    bf16 h0 = __float2bfloat16_rn(v.x);
    bf16 h1 = __float2bfloat16_rn(v.y);
    bf16 h2 = __float2bfloat16_rn(v.z);
    bf16 h3 = __float2bfloat16_rn(v.w);
    bf16 l0 = __float2bfloat16_rn(v.x - __bfloat162float(h0));
    bf16 l1 = __float2bfloat16_rn(v.y - __bfloat162float(h1));
    bf16 l2 = __float2bfloat16_rn(v.z - __bfloat162float(h2));
    bf16 l3 = __float2bfloat16_rn(v.w - __bfloat162float(h3));
    union { bf16 b[4]; uint2 u; } H, L;
    H.b[0] = h0; H.b[1] = h1; H.b[2] = h2; H.b[3] = h3;
    L.b[0] = l0; L.b[1] = l1; L.b[2] = l2; L.b[3] = l3;
    *(uint2*)(hi + 4 * (size_t)i) = H.u;
    *(uint2*)(lo + 4 * (size_t)i) = L.u;
}

// ---------------------------------------------------------------------------
// GEMM mainloop: D(128x128) = A(128xE) @ B(128xE)^T with 3x bf16 split.
// 256 threads = 8 warps (2x4). Warp tile 64x32 = 4x4 m16n8k16 mma tiles.
// SMEM rows padded to 80B -> conflict-free ldmatrix. 3-stage cp.async.
// Result left in smem as float with row stride 132.
// ---------------------------------------------------------------------------
#define KC 32
#define STAGES 3
#define ROWB 80
#define TILE_BYTES (128 * ROWB)          // 10240
#define STAGE_BYTES (4 * TILE_BYTES)     // 40960
#define GEMM_SMEM (STAGES * STAGE_BYTES) // 122880
#define NSTG (E_DIM / KC)                // 32

__device__ __forceinline__ void mma_mainloop(
    const bf16* __restrict__ Ah, const bf16* __restrict__ Al,
    const bf16* __restrict__ Bh, const bf16* __restrict__ Bl,
    int m0, int n0, char* smem)
{
    const int tid = threadIdx.x, lane = tid & 31, wid = tid >> 5;
    const int wr = wid >> 2, wc = wid & 3;
    const uint32_t smb = smem_u32(smem);

    const bf16* Ahb = Ah + (size_t)m0 * E_DIM;
    const bf16* Alb = Al + (size_t)m0 * E_DIM;
    const bf16* Bhb = Bh + (size_t)n0 * E_DIM;
    const bf16* Blb = Bl + (size_t)n0 * E_DIM;

    float acc[4][4][4];
    #pragma unroll
    for (int a = 0; a < 4; ++a)
        #pragma unroll
        for (int b = 0; b < 4; ++b)
            #pragma unroll
            for (int c = 0; c < 4; ++c) acc[a][b][c] = 0.f;

    auto issue = [&](int s) {
        const int buf = s % STAGES;
        const uint32_t db = smb + buf * STAGE_BYTES;
        #pragma unroll
        for (int u = 0; u < 2; ++u) {
            const int ci = tid + 256 * u;
            const int row = ci >> 2, kc = ci & 3;
            const uint32_t doff = row * ROWB + kc * 16;
            const size_t soff = (size_t)row * E_DIM + s * KC + kc * 8;
            cp16(db + doff,                  Ahb + soff);
            cp16(db + TILE_BYTES + doff,     Alb + soff);
            cp16(db + 2 * TILE_BYTES + doff, Bhb + soff);
            cp16(db + 3 * TILE_BYTES + doff, Blb + soff);
        }
        CP_COMMIT();
    };

    // ldmatrix per-lane address components
    const int aRow = lane & 15;
    const int aColB = (lane >> 4) * 16;        // bytes
    const int bRow = lane & 7;
    const int bColB = ((lane >> 3) & 1) * 16;  // bytes

    issue(0);
    issue(1);

    for (int s = 0; s < NSTG; ++s) {
        CP_WAIT(1);
        __syncthreads();
        if (s + 2 < NSTG) issue(s + 2);

        const uint32_t db = smb + (s % STAGES) * STAGE_BYTES;
        #pragma unroll
        for (int ks = 0; ks < 2; ++ks) {
            const int kb = ks * 32;  // 16 bf16 = 32 bytes per k-step
            uint32_t ah[4][4], al[4][4], bh[4][2], bl[4][2];
            #pragma unroll
            for (int mt = 0; mt < 4; ++mt) {
                const uint32_t ra =
                    db + (wr * 64 + mt * 16 + aRow) * ROWB + kb + aColB;
                ldm_x4(ah[mt], ra);
                ldm_x4(al[mt], ra + TILE_BYTES);
            }
            #pragma unroll
            for (int nt = 0; nt < 4; ++nt) {
                const uint32_t rb = db + 2 * TILE_BYTES +
                    (wc * 32 + nt * 8 + bRow) * ROWB + kb + bColB;
                ldm_x2(bh[nt], rb);
                ldm_x2(bl[nt], rb + TILE_BYTES);
            }
            #pragma unroll
            for (int mt = 0; mt < 4; ++mt)
                #pragma unroll
                for (int nt = 0; nt < 4; ++nt) {
                    mma_bf16(acc[mt][nt], ah[mt], bh[nt]);
                    mma_bf16(acc[mt][nt], ah[mt], bl[nt]);
                    mma_bf16(acc[mt][nt], al[mt], bh[nt]);
                }
        }
    }
    __syncthreads();

    // dump accumulators to smem (float, row stride 132)
    float* smf = (float*)smem;
    #pragma unroll
    for (int mt = 0; mt < 4; ++mt)
        #pragma unroll
        for (int nt = 0; nt < 4; ++nt) {
            const int r0 = wr * 64 + mt * 16 + (lane >> 2);
            const int c0 = wc * 32 + nt * 8 + (lane & 3) * 2;
            *(float2*)&smf[r0 * 132 + c0] =
                make_float2(acc[mt][nt][0], acc[mt][nt][1]);
            *(float2*)&smf[(r0 + 8) * 132 + c0] =
                make_float2(acc[mt][nt][2], acc[mt][nt][3]);
        }
    __syncthreads();
}

// ---------------------------------------------------------------------------
// Input projection (mma): out scattered to (b,h,t,d)
// ---------------------------------------------------------------------------
__global__ __launch_bounds__(256, 1) void tc_inproj(const float* __restrict__ bias)
{
    extern __shared__ char smem[];
    const int z = blockIdx.z;
    const int m0 = blockIdx.y * 128, n0 = blockIdx.x * 128;

    mma_mainloop(g_xh + (size_t)z * TB * E_DIM, g_xl + (size_t)z * TB * E_DIM,
                 g_wh + (size_t)z * E_DIM * E_DIM, g_wl + (size_t)z * E_DIM * E_DIM,
                 m0, n0, smem);

    const float* bz = bias + z * E_DIM;
    float* outb = (z == 0) ? g_q : ((z == 1) ? g_k : g_v);
    const int tid = threadIdx.x;
    const int row = tid >> 1, seg = tid & 1;
    const int m = m0 + row;
    const int t = m >> 1, b = m & 1;
    const int nb = n0 + seg * 64;
    const int h = nb >> 6;
    float* dst = outb + (((size_t)(b * H_NUM + h) * T_LEN + t) * D_DIM);
    const float* src = (const float*)smem + row * 132 + seg * 64;
    #pragma unroll
    for (int j = 0; j < 16; ++j) {
        float4 v = *(const float4*)(src + j * 4);
        v.x += bz[nb + j * 4 + 0];
        v.y += bz[nb + j * 4 + 1];
        v.z += bz[nb + j * 4 + 2];
        v.w += bz[nb + j * 4 + 3];
        *(float4*)(dst + j * 4) = v;
    }
}

// ---------------------------------------------------------------------------
// Output projection (mma): out = attn @ Wo^T + bo
// ---------------------------------------------------------------------------
__global__ __launch_bounds__(256, 1) void tc_outproj(
    const float* __restrict__ bias, float* __restrict__ out)
{
    extern __shared__ char smem[];
    const int m0 = blockIdx.y * 128, n0 = blockIdx.x * 128;

    mma_mainloop(g_ah, g_al,
                 g_wh + (size_t)3 * E_DIM * E_DIM, g_wl + (size_t)3 * E_DIM * E_DIM,
                 m0, n0, smem);

    const int tid = threadIdx.x;
    const int row = tid >> 1, seg = tid & 1;
    const int m = m0 + row;
    const int nb = n0 + seg * 64;
    float* dst = out + (size_t)m * E_DIM + nb;
    const float* src = (const float*)smem + row * 132 + seg * 64;
    #pragma unroll
    for (int j = 0; j < 16; ++j) {
        float4 v = *(const float4*)(src + j * 4);
        v.x += bias[nb + j * 4 + 0];
        v.y += bias[nb + j * 4 + 1];
        v.z += bias[nb + j * 4 + 2];
        v.w += bias[nb + j * 4 + 3];
        *(float4*)(dst + j * 4) = v;
    }
}

// ---------------------------------------------------------------------------
// Pass A: per (head, chunk) compute KV_c = K_c^T V_c  (64x64, depth 128)
// ---------------------------------------------------------------------------
__global__ __launch_bounds__(256) void kvchunk_kernel()
{
    const int c = blockIdx.x, bh = blockIdx.y;
    const float* Kg = g_k + (bh * T_LEN + c * CH) * D_DIM;
    const float* Vg = g_v + (bh * T_LEN + c * CH) * D_DIM;
    __shared__ float Ks[32 * 64];
    __shared__ float Vs[32 * 64];
    const int tid = threadIdx.x;
    const int tx = tid & 15, ty = tid >> 4;

    ull acc[4][2];
    #pragma unroll
    for (int i = 0; i < 4; ++i) { acc[i][0] = 0ull; acc[i][1] = 0ull; }

    for (int s0 = 0; s0 < CH; s0 += 32) {
        __syncthreads();
        #pragma unroll
        for (int u = 0; u < 2; ++u) {
            const int idx = tid * 4 + u * 1024;
            *(float4*)&Ks[idx] = *(const float4*)&Kg[s0 * 64 + idx];
            *(float4*)&Vs[idx] = *(const float4*)&Vg[s0 * 64 + idx];
        }
        __syncthreads();
        #pragma unroll 8
        for (int ss = 0; ss < 32; ++ss) {
            float4 kq = *(const float4*)&Ks[ss * 64 + ty * 4];
            ulonglong2 vv = *(const ulonglong2*)&Vs[ss * 64 + tx * 4];
            ull kd[4] = {dup2(kq.x), dup2(kq.y), dup2(kq.z), dup2(kq.w)};
            #pragma unroll
            for (int i = 0; i < 4; ++i) {
                fma2(acc[i][0], kd[i], vv.x);
                fma2(acc[i][1], kd[i], vv.y);
            }
        }
    }

    float* outp = g_kvc + (bh * NC + c) * D_DIM * D_DIM;
    #pragma unroll
    for (int i = 0; i < 4; ++i) {
        float2 r0 = unpk(acc[i][0]);
        float2 r1 = unpk(acc[i][1]);
        float* dst = &outp[(ty * 4 + i) * 64 + tx * 4];
        dst[0] = r0.x; dst[1] = r0.y; dst[2] = r1.x; dst[3] = r1.y;
    }
}

// ---------------------------------------------------------------------------
// Pass B: exclusive prefix-sum of chunk KV states over the 8 chunks
// ---------------------------------------------------------------------------
__global__ __launch_bounds__(256) void scan_kernel()
{
    const int bh = blockIdx.x;
    for (int e = threadIdx.x; e < D_DIM * D_DIM; e += 256) {
        float s = 0.f;
        #pragma unroll
        for (int c = 0; c < NC; ++c) {
            g_ssum[(bh * NC + c) * D_DIM * D_DIM + e] = s;
            s += g_kvc[(bh * NC + c) * D_DIM * D_DIM + e];
        }
    }
}

// ---------------------------------------------------------------------------
// Pass C: per (head, chunk): O_c = (Q_c @ S_c + tril(Q_c K_c^T) @ V_c) * scale
// ---------------------------------------------------------------------------
#define SMEM_C_FLOATS (128 * 65 + 128 * 65 + 128 * 64 + 64 * 64 + 128 * 128)
#define SMEM_C_BYTES (SMEM_C_FLOATS * 4)

__global__ __launch_bounds__(256) void attn_kernel()
{
    extern __shared__ float smc[];
    float* Qs = smc;                   // 128 x 65 (padded)
    float* Ks = Qs + 128 * 65;         // 128 x 65 (padded)
    float* Vs = Ks + 128 * 65;         // 128 x 64
    float* Ss = Vs + 128 * 64;         // 64 x 64
    float* Ps = Ss + 64 * 64;          // 128 x 128

    const int c = blockIdx.x, bh = blockIdx.y;
    const int tid = threadIdx.x;
    const float* Qg = g_q + (bh * T_LEN + c * CH) * D_DIM;
    const float* Kg = g_k + (bh * T_LEN + c * CH) * D_DIM;
    const float* Vg = g_v + (bh * T_LEN + c * CH) * D_DIM;
    const float* Sg = g_ssum + (bh * NC + c) * D_DIM * D_DIM;

    for (int idx = tid * 4; idx < CH * D_DIM; idx += 256 * 4) {
        const int row = idx >> 6, col = idx & 63;
        float4 q4 = *(const float4*)&Qg[idx];
        float4 k4 = *(const float4*)&Kg[idx];
        *(float4*)&Vs[idx] = *(const float4*)&Vg[idx];
        Qs[row * 65 + col + 0] = q4.x; Qs[row * 65 + col + 1] = q4.y;
        Qs[row * 65 + col + 2] = q4.z; Qs[row * 65 + col + 3] = q4.w;
        Ks[row * 65 + col + 0] = k4.x; Ks[row * 65 + col + 1] = k4.y;
        Ks[row * 65 + col + 2] = k4.z; Ks[row * 65 + col + 3] = k4.w;
    }
    for (int idx = tid * 4; idx < D_DIM * D_DIM; idx += 256 * 4)
        *(float4*)&Ss[idx] = *(const float4*)&Sg[idx];
    __syncthreads();

    const int tx = tid & 15, ty = tid >> 4;

    // P = tril(Q K^T)
    {
        float p[8][8];
        #pragma unroll
        for (int i = 0; i < 8; ++i)
            #pragma unroll
            for (int j = 0; j < 8; ++j) p[i][j] = 0.f;

        #pragma unroll 4
        for (int d = 0; d < D_DIM; ++d) {
            float qf[8], kf[8];
            #pragma unroll
            for (int i = 0; i < 8; ++i) qf[i] = Qs[(ty * 8 + i) * 65 + d];
            #pragma unroll
            for (int j = 0; j < 8; ++j) kf[j] = Ks[(tx * 8 + j) * 65 + d];
            #pragma unroll
            for (int i = 0; i < 8; ++i)
                #pragma unroll
                for (int j = 0; j < 8; ++j)
                    p[i][j] = fmaf(qf[i], kf[j], p[i][j]);
        }
        #pragma unroll
        for (int i = 0; i < 8; ++i) {
            const int i_ = ty * 8 + i;
            #pragma unroll
            for (int j = 0; j < 8; ++j) {
                const int j_ = tx * 8 + j;
                Ps[i_ * 128 + j_] = (j_ <= i_) ? p[i][j] : 0.f;
            }
        }
    }
    __syncthreads();

    // O = Q @ S + P @ V
    {
        const int v0 = tx * 4;
        const int i0 = ty * 8;
        ull o[8][2];
        #pragma unroll
        for (int i = 0; i < 8; ++i) { o[i][0] = 0ull; o[i][1] = 0ull; }

        #pragma unroll 4
        for (int k = 0; k < D_DIM; ++k) {
            ulonglong2 sp = *(const ulonglong2*)&Ss[k * 64 + v0];
            #pragma unroll
            for (int i = 0; i < 8; ++i) {
                ull qd = dup2(Qs[(i0 + i) * 65 + k]);
                fma2(o[i][0], qd, sp.x);
                fma2(o[i][1], qd, sp.y);
            }
        }
        #pragma unroll 4
        for (int j2 = 0; j2 < CH; ++j2) {
            ulonglong2 vp = *(const ulonglong2*)&Vs[j2 * 64 + v0];
            #pragma unroll
            for (int i = 0; i < 8; ++i) {
                ull pd = dup2(Ps[(i0 + i) * 128 + j2]);
                fma2(o[i][0], pd, vp.x);
                fma2(o[i][1], pd, vp.y);
            }
        }

        const int b = bh / H_NUM, h = bh % H_NUM;
        #pragma unroll
        for (int i = 0; i < 8; ++i) {
            const int t = c * CH + i0 + i;
            float* dst = g_attn + (t * B_SZ + b) * E_DIM + h * D_DIM + v0;
            float2 r0 = unpk(o[i][0]);
            float2 r1 = unpk(o[i][1]);
            dst[0] = r0.x * SCALE_ATT; dst[1] = r0.y * SCALE_ATT;
            dst[2] = r1.x * SCALE_ATT; dst[3] = r1.y * SCALE_ATT;
        }
    }
}

// ---------------------------------------------------------------------------
extern "C" void kernel_launch(void* const* d_in, const int* in_sizes, int n_in,
                              void* d_out, int out_size)
{
    (void)in_sizes; (void)n_in; (void)out_size;
    const float* query = (const float*)d_in[0];
    const float* key_  = (const float*)d_in[1];
    const float* value = (const float*)d_in[2];
    const float* ipw   = (const float*)d_in[3];
    const float* ipb   = (const float*)d_in[4];
    const float* opw   = (const float*)d_in[5];
    const float* opb   = (const float*)d_in[6];
    float* out = (float*)d_out;

    cudaFuncSetAttribute(tc_inproj,
                         cudaFuncAttributeMaxDynamicSharedMemorySize, GEMM_SMEM);
    cudaFuncSetAttribute(tc_outproj,
                         cudaFuncAttributeMaxDynamicSharedMemorySize, GEMM_SMEM);
    cudaFuncSetAttribute(attn_kernel,
                         cudaFuncAttributeMaxDynamicSharedMemorySize, SMEM_C_BYTES);

    const int NX = TB * E_DIM;          // 2,097,152
    const int NW = E_DIM * E_DIM;       // 1,048,576

    // Split activations and weights into bf16 hi/lo planes
    split_kernel<<<NX / 1024, 256>>>(query, 0, 0, NX / 4);
    split_kernel<<<NX / 1024, 256>>>(key_,  0, NX, NX / 4);
    split_kernel<<<NX / 1024, 256>>>(value, 0, 2 * NX, NX / 4);
    split_kernel<<<3 * NW / 1024, 256>>>(ipw, 1, 0, 3 * NW / 4);
    split_kernel<<<NW / 1024, 256>>>(opw, 1, 3 * NW, NW / 4);

    // Input projection on tensor pipe
    tc_inproj<<<dim3(E_DIM / 128, TB / 128, 3), 256, GEMM_SMEM>>>(ipb);

    // Chunked causal linear attention (fp32)
    kvchunk_kernel<<<dim3(NC, BHN), 256>>>();
    scan_kernel<<<BHN, 256>>>();
    attn_kernel<<<dim3(NC, BHN), 256, SMEM_C_BYTES>>>();

    // Split attention output, then output projection on tensor pipe
    split_kernel<<<NX / 1024, 256>>>(nullptr, 2, 0, NX / 4);
    tc_outproj<<<dim3(E_DIM / 128, TB / 128), 256, GEMM_SMEM>>>(opb, out);
}

// round 5
// speedup vs baseline: 2.2133x; 1.0415x over previous
#include <cuda_runtime.h>
#include <cuda_bf16.h>
#include <cstdint>

// Problem constants
#define T_LEN 1024
#define B_SZ 2
#define E_DIM 1024
#define H_NUM 16
#define D_DIM 64
#define TB (T_LEN * B_SZ)          // 2048
#define CH 128                     // chunk length
#define NC (T_LEN / CH)            // 8 chunks
#define BHN (B_SZ * H_NUM)         // 32 head-batches
#define SCALE_ATT 0.125f           // 1/sqrt(64)

typedef unsigned long long ull;
typedef __nv_bfloat16 bf16;

// Scratch (device globals; no allocation allowed)
__device__ float g_k[BHN * T_LEN * D_DIM];     // fp32 for kvchunk
__device__ float g_v[BHN * T_LEN * D_DIM];
__device__ float g_kvc[BHN * NC * D_DIM * D_DIM];
__device__ float g_ssum[BHN * NC * D_DIM * D_DIM];

// bf16 hi/lo planes
__device__ __align__(16) bf16 g_xh[3 * TB * E_DIM];
__device__ __align__(16) bf16 g_xl[3 * TB * E_DIM];
__device__ __align__(16) bf16 g_wh[4 * E_DIM * E_DIM];
__device__ __align__(16) bf16 g_wl[4 * E_DIM * E_DIM];
__device__ __align__(16) bf16 g_ah[TB * E_DIM];      // attn out (t*B+b, e)
__device__ __align__(16) bf16 g_al[TB * E_DIM];
// (b,h,t,d) planes for attention
__device__ __align__(16) bf16 g_qh[BHN * T_LEN * D_DIM];
__device__ __align__(16) bf16 g_ql[BHN * T_LEN * D_DIM];
__device__ __align__(16) bf16 g_kh[BHN * T_LEN * D_DIM];
__device__ __align__(16) bf16 g_kl[BHN * T_LEN * D_DIM];
__device__ __align__(16) bf16 g_vh[BHN * T_LEN * D_DIM];
__device__ __align__(16) bf16 g_vl[BHN * T_LEN * D_DIM];

// ---- packed f32x2 helpers (kvchunk) -----------------------------------------
__device__ __forceinline__ void fma2(ull& d, ull a, ull b) {
    asm("fma.rn.f32x2 %0, %1, %2, %0;" : "+l"(d) : "l"(a), "l"(b));
}
__device__ __forceinline__ ull dup2(float x) {
    ull r; asm("mov.b64 %0, {%1, %1};" : "=l"(r) : "f"(x)); return r;
}
__device__ __forceinline__ float2 unpk(ull v) {
    float2 r; asm("mov.b64 {%0, %1}, %2;" : "=f"(r.x), "=f"(r.y) : "l"(v)); return r;
}

// ---- mma.sync helpers --------------------------------------------------------
__device__ __forceinline__ uint32_t smem_u32(const void* p) {
    uint32_t a;
    asm("{ .reg .u64 t; cvta.to.shared.u64 t, %1; cvt.u32.u64 %0, t; }"
        : "=r"(a) : "l"(p));
    return a;
}
__device__ __forceinline__ void cp16(uint32_t dst, const void* src) {
    asm volatile("cp.async.ca.shared.global [%0], [%1], 16;"
                 :: "r"(dst), "l"(src) : "memory");
}
#define CP_COMMIT() asm volatile("cp.async.commit_group;" ::: "memory")
#define CP_WAIT(n)  asm volatile("cp.async.wait_group %0;" :: "n"(n) : "memory")

__device__ __forceinline__ void ldm_x4(uint32_t* r, uint32_t addr) {
    asm volatile("ldmatrix.sync.aligned.m8n8.x4.shared.b16 {%0,%1,%2,%3}, [%4];"
                 : "=r"(r[0]), "=r"(r[1]), "=r"(r[2]), "=r"(r[3]) : "r"(addr));
}
__device__ __forceinline__ void ldm_x2(uint32_t* r, uint32_t addr) {
    asm volatile("ldmatrix.sync.aligned.m8n8.x2.shared.b16 {%0,%1}, [%2];"
                 : "=r"(r[0]), "=r"(r[1]) : "r"(addr));
}
__device__ __forceinline__ void mma_bf16(float* c, const uint32_t* a, const uint32_t* b) {
    asm volatile(
        "mma.sync.aligned.m16n8k16.row.col.f32.bf16.bf16.f32 "
        "{%0,%1,%2,%3}, {%4,%5,%6,%7}, {%8,%9}, {%0,%1,%2,%3};"
        : "+f"(c[0]), "+f"(c[1]), "+f"(c[2]), "+f"(c[3])
        : "r"(a[0]), "r"(a[1]), "r"(a[2]), "r"(a[3]), "r"(b[0]), "r"(b[1]));
}
__device__ __forceinline__ uint32_t pk2(float lo, float hi) {
    __nv_bfloat162 t = __floats2bfloat162_rn(lo, hi);
    return *(uint32_t*)&t;
}

// ---------------------------------------------------------------------------
// Split kernels: fp32 -> (hi, lo) bf16 planes
// ---------------------------------------------------------------------------
__global__ __launch_bounds__(256) void split_act(
    const float* __restrict__ q, const float* __restrict__ k,
    const float* __restrict__ v)
{
    const int z = blockIdx.z;
    const float* s = (z == 0) ? q : ((z == 1) ? k : v);
    const size_t i = blockIdx.x * 256 + threadIdx.x;
    float4 x = ((const float4*)s)[i];
    bf16* hi = g_xh + (size_t)z * TB * E_DIM + 4 * i;
    bf16* lo = g_xl + (size_t)z * TB * E_DIM + 4 * i;
    union { bf16 b[4]; uint2 u; } H, L;
    H.b[0] = __float2bfloat16_rn(x.x); L.b[0] = __float2bfloat16_rn(x.x - __bfloat162float(H.b[0]));
    H.b[1] = __float2bfloat16_rn(x.y); L.b[1] = __float2bfloat16_rn(x.y - __bfloat162float(H.b[1]));
    H.b[2] = __float2bfloat16_rn(x.z); L.b[2] = __float2bfloat16_rn(x.z - __bfloat162float(H.b[2]));
    H.b[3] = __float2bfloat16_rn(x.w); L.b[3] = __float2bfloat16_rn(x.w - __bfloat162float(H.b[3]));
    *(uint2*)hi = H.u;
    *(uint2*)lo = L.u;
}

__global__ __launch_bounds__(256) void split_w(
    const float* __restrict__ ipw, const float* __restrict__ opw)
{
    const size_t i = blockIdx.x * 256 + threadIdx.x;   // over 4*NW/4
    const size_t LIM = (size_t)3 * E_DIM * E_DIM / 4;
    float4 x = (i < LIM) ? ((const float4*)ipw)[i] : ((const float4*)opw)[i - LIM];
    union { bf16 b[4]; uint2 u; } H, L;
    H.b[0] = __float2bfloat16_rn(x.x); L.b[0] = __float2bfloat16_rn(x.x - __bfloat162float(H.b[0]));
    H.b[1] = __float2bfloat16_rn(x.y); L.b[1] = __float2bfloat16_rn(x.y - __bfloat162float(H.b[1]));
    H.b[2] = __float2bfloat16_rn(x.z); L.b[2] = __float2bfloat16_rn(x.z - __bfloat162float(H.b[2]));
    H.b[3] = __float2bfloat16_rn(x.w); L.b[3] = __float2bfloat16_rn(x.w - __bfloat162float(H.b[3]));
    *(uint2*)(g_wh + 4 * i) = H.u;
    *(uint2*)(g_wl + 4 * i) = L.u;
}

// ---------------------------------------------------------------------------
// GEMM mainloop (unchanged from R4): D(128x128) = A @ B^T, 3x bf16 split
// ---------------------------------------------------------------------------
#define KC 32
#define STAGES 3
#define ROWB 80
#define TILE_BYTES (128 * ROWB)
#define STAGE_BYTES (4 * TILE_BYTES)
#define GEMM_SMEM (STAGES * STAGE_BYTES)
#define NSTG (E_DIM / KC)

__device__ __forceinline__ void mma_mainloop(
    const bf16* __restrict__ Ah, const bf16* __restrict__ Al,
    const bf16* __restrict__ Bh, const bf16* __restrict__ Bl,
    int m0, int n0, char* smem)
{
    const int tid = threadIdx.x, lane = tid & 31, wid = tid >> 5;
    const int wr = wid >> 2, wc = wid & 3;
    const uint32_t smb = smem_u32(smem);

    const bf16* Ahb = Ah + (size_t)m0 * E_DIM;
    const bf16* Alb = Al + (size_t)m0 * E_DIM;
    const bf16* Bhb = Bh + (size_t)n0 * E_DIM;
    const bf16* Blb = Bl + (size_t)n0 * E_DIM;

    float acc[4][4][4];
    #pragma unroll
    for (int a = 0; a < 4; ++a)
        #pragma unroll
        for (int b = 0; b < 4; ++b)
            #pragma unroll
            for (int c = 0; c < 4; ++c) acc[a][b][c] = 0.f;

    auto issue = [&](int s) {
        const int buf = s % STAGES;
        const uint32_t db = smb + buf * STAGE_BYTES;
        #pragma unroll
        for (int u = 0; u < 2; ++u) {
            const int ci = tid + 256 * u;
            const int row = ci >> 2, kc = ci & 3;
            const uint32_t doff = row * ROWB + kc * 16;
            const size_t soff = (size_t)row * E_DIM + s * KC + kc * 8;
            cp16(db + doff,                  Ahb + soff);
            cp16(db + TILE_BYTES + doff,     Alb + soff);
            cp16(db + 2 * TILE_BYTES + doff, Bhb + soff);
            cp16(db + 3 * TILE_BYTES + doff, Blb + soff);
        }
        CP_COMMIT();
    };

    const int aRow = lane & 15;
    const int aColB = (lane >> 4) * 16;
    const int bRow = lane & 7;
    const int bColB = ((lane >> 3) & 1) * 16;

    issue(0);
    issue(1);

    for (int s = 0; s < NSTG; ++s) {
        CP_WAIT(1);
        __syncthreads();
        if (s + 2 < NSTG) issue(s + 2);

        const uint32_t db = smb + (s % STAGES) * STAGE_BYTES;
        #pragma unroll
        for (int ks = 0; ks < 2; ++ks) {
            const int kb = ks * 32;
            uint32_t ah[4][4], al[4][4], bh[4][2], bl[4][2];
            #pragma unroll
            for (int mt = 0; mt < 4; ++mt) {
                const uint32_t ra =
                    db + (wr * 64 + mt * 16 + aRow) * ROWB + kb + aColB;
                ldm_x4(ah[mt], ra);
                ldm_x4(al[mt], ra + TILE_BYTES);
            }
            #pragma unroll
            for (int nt = 0; nt < 4; ++nt) {
                const uint32_t rb = db + 2 * TILE_BYTES +
                    (wc * 32 + nt * 8 + bRow) * ROWB + kb + bColB;
                ldm_x2(bh[nt], rb);
                ldm_x2(bl[nt], rb + TILE_BYTES);
            }
            #pragma unroll
            for (int mt = 0; mt < 4; ++mt)
                #pragma unroll
                for (int nt = 0; nt < 4; ++nt) {
                    mma_bf16(acc[mt][nt], ah[mt], bh[nt]);
                    mma_bf16(acc[mt][nt], ah[mt], bl[nt]);
                    mma_bf16(acc[mt][nt], al[mt], bh[nt]);
                }
        }
    }
    __syncthreads();

    float* smf = (float*)smem;
    #pragma unroll
    for (int mt = 0; mt < 4; ++mt)
        #pragma unroll
        for (int nt = 0; nt < 4; ++nt) {
            const int r0 = wr * 64 + mt * 16 + (lane >> 2);
            const int c0 = wc * 32 + nt * 8 + (lane & 3) * 2;
            *(float2*)&smf[r0 * 132 + c0] =
                make_float2(acc[mt][nt][0], acc[mt][nt][1]);
            *(float2*)&smf[(r0 + 8) * 132 + c0] =
                make_float2(acc[mt][nt][2], acc[mt][nt][3]);
        }
    __syncthreads();
}

// ---------------------------------------------------------------------------
// Input projection: writes bf16 hi/lo planes (q,k,v) + fp32 (k,v only)
// ---------------------------------------------------------------------------
__global__ __launch_bounds__(256, 1) void tc_inproj(const float* __restrict__ bias)
{
    extern __shared__ char smem[];
    const int z = blockIdx.z;
    const int m0 = blockIdx.y * 128, n0 = blockIdx.x * 128;

    mma_mainloop(g_xh + (size_t)z * TB * E_DIM, g_xl + (size_t)z * TB * E_DIM,
                 g_wh + (size_t)z * E_DIM * E_DIM, g_wl + (size_t)z * E_DIM * E_DIM,
                 m0, n0, smem);

    const float* bz = bias + z * E_DIM;
    bf16* ph = (z == 0) ? g_qh : ((z == 1) ? g_kh : g_vh);
    bf16* pl = (z == 0) ? g_ql : ((z == 1) ? g_kl : g_vl);
    float* outf = (z == 1) ? g_k : ((z == 2) ? g_v : nullptr);

    const int tid = threadIdx.x;
    const int row = tid >> 1, seg = tid & 1;
    const int m = m0 + row;
    const int t = m >> 1, b = m & 1;
    const int nb = n0 + seg * 64;
    const int h = nb >> 6;
    const size_t base = ((size_t)(b * H_NUM + h) * T_LEN + t) * D_DIM;
    const float* src = (const float*)smem + row * 132 + seg * 64;
    #pragma unroll
    for (int j = 0; j < 16; ++j) {
        float4 v = *(const float4*)(src + j * 4);
        v.x += bz[nb + j * 4 + 0];
        v.y += bz[nb + j * 4 + 1];
        v.z += bz[nb + j * 4 + 2];
        v.w += bz[nb + j * 4 + 3];
        if (outf) *(float4*)(outf + base + j * 4) = v;
        union { bf16 b[4]; uint2 u; } H, L;
        H.b[0] = __float2bfloat16_rn(v.x); L.b[0] = __float2bfloat16_rn(v.x - __bfloat162float(H.b[0]));
        H.b[1] = __float2bfloat16_rn(v.y); L.b[1] = __float2bfloat16_rn(v.y - __bfloat162float(H.b[1]));
        H.b[2] = __float2bfloat16_rn(v.z); L.b[2] = __float2bfloat16_rn(v.z - __bfloat162float(H.b[2]));
        H.b[3] = __float2bfloat16_rn(v.w); L.b[3] = __float2bfloat16_rn(v.w - __bfloat162float(H.b[3]));
        *(uint2*)(ph + base + j * 4) = H.u;
        *(uint2*)(pl + base + j * 4) = L.u;
    }
}

// ---------------------------------------------------------------------------
// Output projection: out = attn @ Wo^T + bo
// ---------------------------------------------------------------------------
__global__ __launch_bounds__(256, 1) void tc_outproj(
    const float* __restrict__ bias, float* __restrict__ out)
{
    extern __shared__ char smem[];
    const int m0 = blockIdx.y * 128, n0 = blockIdx.x * 128;

    mma_mainloop(g_ah, g_al,
                 g_wh + (size_t)3 * E_DIM * E_DIM, g_wl + (size_t)3 * E_DIM * E_DIM,
                 m0, n0, smem);

    const int tid = threadIdx.x;
    const int row = tid >> 1, seg = tid & 1;
    const int m = m0 + row;
    const int nb = n0 + seg * 64;
    float* dst = out + (size_t)m * E_DIM + nb;
    const float* src = (const float*)smem + row * 132 + seg * 64;
    #pragma unroll
    for (int j = 0; j < 16; ++j) {
        float4 v = *(const float4*)(src + j * 4);
        v.x += bias[nb + j * 4 + 0];
        v.y += bias[nb + j * 4 + 1];
        v.z += bias[nb + j * 4 + 2];
        v.w += bias[nb + j * 4 + 3];
        *(float4*)(dst + j * 4) = v;
    }
}

// ---------------------------------------------------------------------------
// Pass A: per (head, chunk) KV_c = K_c^T V_c  (fp32)
// ---------------------------------------------------------------------------
__global__ __launch_bounds__(256) void kvchunk_kernel()
{
    const int c = blockIdx.x, bh = blockIdx.y;
    const float* Kg = g_k + (bh * T_LEN + c * CH) * D_DIM;
    const float* Vg = g_v + (bh * T_LEN + c * CH) * D_DIM;
    __shared__ float Ks[32 * 64];
    __shared__ float Vs[32 * 64];
    const int tid = threadIdx.x;
    const int tx = tid & 15, ty = tid >> 4;

    ull acc[4][2];
    #pragma unroll
    for (int i = 0; i < 4; ++i) { acc[i][0] = 0ull; acc[i][1] = 0ull; }

    for (int s0 = 0; s0 < CH; s0 += 32) {
        __syncthreads();
        #pragma unroll
        for (int u = 0; u < 2; ++u) {
            const int idx = tid * 4 + u * 1024;
            *(float4*)&Ks[idx] = *(const float4*)&Kg[s0 * 64 + idx];
            *(float4*)&Vs[idx] = *(const float4*)&Vg[s0 * 64 + idx];
        }
        __syncthreads();
        #pragma unroll 8
        for (int ss = 0; ss < 32; ++ss) {
            float4 kq = *(const float4*)&Ks[ss * 64 + ty * 4];
            ulonglong2 vv = *(const ulonglong2*)&Vs[ss * 64 + tx * 4];
            ull kd[4] = {dup2(kq.x), dup2(kq.y), dup2(kq.z), dup2(kq.w)};
            #pragma unroll
            for (int i = 0; i < 4; ++i) {
                fma2(acc[i][0], kd[i], vv.x);
                fma2(acc[i][1], kd[i], vv.y);
            }
        }
    }

    float* outp = g_kvc + (bh * NC + c) * D_DIM * D_DIM;
    #pragma unroll
    for (int i = 0; i < 4; ++i) {
        float2 r0 = unpk(acc[i][0]);
        float2 r1 = unpk(acc[i][1]);
        float* dst = &outp[(ty * 4 + i) * 64 + tx * 4];
        dst[0] = r0.x; dst[1] = r0.y; dst[2] = r1.x; dst[3] = r1.y;
    }
}

// ---------------------------------------------------------------------------
// Pass B: exclusive prefix-sum over chunks
// ---------------------------------------------------------------------------
__global__ __launch_bounds__(256) void scan_kernel()
{
    const int bh = blockIdx.x;
    for (int e = threadIdx.x; e < D_DIM * D_DIM; e += 256) {
        float s = 0.f;
        #pragma unroll
        for (int c = 0; c < NC; ++c) {
            g_ssum[(bh * NC + c) * D_DIM * D_DIM + e] = s;
            s += g_kvc[(bh * NC + c) * D_DIM * D_DIM + e];
        }
    }
}

// ---------------------------------------------------------------------------
// Pass C (mma): O_c = (Q_c @ S_c + tril(Q_c K_c^T) @ V_c) * scale
// 8 warps, warp w owns rows [w*16, w*16+16). P C-fragments reused as
// A-fragments for P@V (no smem round trip, no cross-warp reduction).
// ---------------------------------------------------------------------------
#define AQS 144                         // 64-bf16 row stride (128B + 16 pad)
#define AVS 272                         // 128-bf16 row stride (256B + 16 pad)
#define SM_QH 0
#define SM_QL (128 * AQS)
#define SM_KH (2 * 128 * AQS)
#define SM_KL (3 * 128 * AQS)
#define SM_VTH (4 * 128 * AQS)          // V^T: 64 rows x 128 cols
#define SM_VTL (SM_VTH + 64 * AVS)
#define SM_STH (SM_VTL + 64 * AVS)      // S^T: 64 rows x 64 cols
#define SM_STL (SM_STH + 64 * AQS)
#define ATT_SMEM (SM_STL + 64 * AQS)    // 126976 bytes

__global__ __launch_bounds__(256, 1) void attn_mma_kernel()
{
    extern __shared__ char smem[];
    const int c = blockIdx.x, bh = blockIdx.y;
    const int tid = threadIdx.x, lane = tid & 31, w = tid >> 5;
    const uint32_t smb = smem_u32(smem);

    const size_t pbase = (size_t)(bh * T_LEN + c * CH) * D_DIM;
    const char* Qhg = (const char*)(g_qh + pbase);
    const char* Qlg = (const char*)(g_ql + pbase);
    const char* Khg = (const char*)(g_kh + pbase);
    const char* Klg = (const char*)(g_kl + pbase);

    // Q/K hi/lo -> smem (128 rows x 128B, stride 144)
    #pragma unroll
    for (int u = 0; u < 4; ++u) {
        const int ci = tid + 256 * u;           // 0..1023
        const int row = ci >> 3, ch = (ci & 7) * 16;
        *(uint4*)(smem + SM_QH + row * AQS + ch) = *(const uint4*)(Qhg + row * 128 + ch);
        *(uint4*)(smem + SM_QL + row * AQS + ch) = *(const uint4*)(Qlg + row * 128 + ch);
        *(uint4*)(smem + SM_KH + row * AQS + ch) = *(const uint4*)(Khg + row * 128 + ch);
        *(uint4*)(smem + SM_KL + row * AQS + ch) = *(const uint4*)(Klg + row * 128 + ch);
    }

    // V transposed: Vt[v][j] = V[j][v]
    {
        const bf16* Vhg = g_vh + pbase;
        const bf16* Vlg = g_vl + pbase;
        #pragma unroll
        for (int u = 0; u < 8; ++u) {
            const int ci = tid + 256 * u;       // 0..2047
            const int j = ci >> 4, g = ci & 15;
            union { uint2 u2; bf16 b[4]; } H, L;
            H.u2 = *(const uint2*)(Vhg + j * 64 + g * 4);
            L.u2 = *(const uint2*)(Vlg + j * 64 + g * 4);
            #pragma unroll
            for (int q = 0; q < 4; ++q) {
                *(bf16*)(smem + SM_VTH + (g * 4 + q) * AVS + j * 2) = H.b[q];
                *(bf16*)(smem + SM_VTL + (g * 4 + q) * AVS + j * 2) = L.b[q];
            }
        }
    }

    // S transposed + split: St[v][k] = S[k][v]
    {
        const float* Sg = g_ssum + (size_t)(bh * NC + c) * D_DIM * D_DIM;
        #pragma unroll
        for (int u = 0; u < 16; ++u) {
            const int idx = tid + 256 * u;      // 0..4095
            const int k = idx >> 6, v = idx & 63;
            float s = Sg[k * 64 + v];
            bf16 h = __float2bfloat16_rn(s);
            bf16 l = __float2bfloat16_rn(s - __bfloat162float(h));
            *(bf16*)(smem + SM_STH + v * AQS + k * 2) = h;
            *(bf16*)(smem + SM_STL + v * AQS + k * 2) = l;
        }
    }
    __syncthreads();

    const int aRow = lane & 15;
    const int aColB = (lane >> 4) * 16;
    const int bRow = lane & 7;
    const int bColB = ((lane >> 3) & 1) * 16;

    // --- Phase 1: O += Q @ S (B = S^T rows) ---
    float oacc[8][4];
    #pragma unroll
    for (int nt = 0; nt < 8; ++nt)
        #pragma unroll
        for (int e = 0; e < 4; ++e) oacc[nt][e] = 0.f;

    #pragma unroll
    for (int ks = 0; ks < 4; ++ks) {
        uint32_t aqh[4], aql[4];
        const uint32_t ra = smb + SM_QH + (w * 16 + aRow) * AQS + ks * 32 + aColB;
        ldm_x4(aqh, ra);
        ldm_x4(aql, ra + (SM_QL - SM_QH));
        #pragma unroll
        for (int nt = 0; nt < 8; ++nt) {
            uint32_t bh2[2], bl2[2];
            const uint32_t rb = smb + SM_STH + (nt * 8 + bRow) * AQS + ks * 32 + bColB;
            ldm_x2(bh2, rb);
            ldm_x2(bl2, rb + (SM_STL - SM_STH));
            mma_bf16(oacc[nt], aqh, bh2);
            mma_bf16(oacc[nt], aqh, bl2);
            mma_bf16(oacc[nt], aql, bh2);
        }
    }

    // --- Phase 2: P = Q K^T (16x128 per warp) ---
    float p[16][4];
    #pragma unroll
    for (int nt = 0; nt < 16; ++nt)
        #pragma unroll
        for (int e = 0; e < 4; ++e) p[nt][e] = 0.f;

    #pragma unroll
    for (int ks = 0; ks < 4; ++ks) {
        uint32_t aqh[4], aql[4];
        const uint32_t ra = smb + SM_QH + (w * 16 + aRow) * AQS + ks * 32 + aColB;
        ldm_x4(aqh, ra);
        ldm_x4(aql, ra + (SM_QL - SM_QH));
        #pragma unroll
        for (int nt = 0; nt < 16; ++nt) {
            uint32_t bh2[2], bl2[2];
            const uint32_t rb = smb + SM_KH + (nt * 8 + bRow) * AQS + ks * 32 + bColB;
            ldm_x2(bh2, rb);
            ldm_x2(bl2, rb + (SM_KL - SM_KH));
            mma_bf16(p[nt], aqh, bh2);
            mma_bf16(p[nt], aqh, bl2);
            mma_bf16(p[nt], aql, bh2);
        }
    }

    // --- Mask (tril) + pack P into A-fragments (hi/lo) ---
    uint32_t phi[16][2], plo[16][2];
    const int r0 = w * 16 + (lane >> 2);
    const int r1 = r0 + 8;
    #pragma unroll
    for (int nt = 0; nt < 16; ++nt) {
        const int cb = nt * 8 + 2 * (lane & 3);
        float p0 = (cb     <= r0) ? p[nt][0] : 0.f;
        float p1 = (cb + 1 <= r0) ? p[nt][1] : 0.f;
        float p2 = (cb     <= r1) ? p[nt][2] : 0.f;
        float p3 = (cb + 1 <= r1) ? p[nt][3] : 0.f;
        bf16 h0 = __float2bfloat16_rn(p0);
        bf16 h1 = __float2bfloat16_rn(p1);
        bf16 h2 = __float2bfloat16_rn(p2);
        bf16 h3 = __float2bfloat16_rn(p3);
        phi[nt][0] = pk2(__bfloat162float(h0), __bfloat162float(h1));
        phi[nt][1] = pk2(__bfloat162float(h2), __bfloat162float(h3));
        plo[nt][0] = pk2(p0 - __bfloat162float(h0), p1 - __bfloat162float(h1));
        plo[nt][1] = pk2(p2 - __bfloat162float(h2), p3 - __bfloat162float(h3));
    }

    // --- Phase 3: O += P @ V (B = V^T rows) ---
    #pragma unroll
    for (int ks = 0; ks < 8; ++ks) {
        uint32_t ah[4] = {phi[2 * ks][0], phi[2 * ks][1],
                          phi[2 * ks + 1][0], phi[2 * ks + 1][1]};
        uint32_t al[4] = {plo[2 * ks][0], plo[2 * ks][1],
                          plo[2 * ks + 1][0], plo[2 * ks + 1][1]};
        #pragma unroll
        for (int nt = 0; nt < 8; ++nt) {
            uint32_t bh2[2], bl2[2];
            const uint32_t rb = smb + SM_VTH + (nt * 8 + bRow) * AVS + ks * 32 + bColB;
            ldm_x2(bh2, rb);
            ldm_x2(bl2, rb + (SM_VTL - SM_VTH));
            mma_bf16(oacc[nt], ah, bh2);
            mma_bf16(oacc[nt], ah, bl2);
            mma_bf16(oacc[nt], al, bh2);
        }
    }

    // --- Epilogue: scale, split hi/lo, write g_ah/g_al at (t*B+b, e) ---
    const int bb = bh / H_NUM, hh = bh % H_NUM;
    #pragma unroll
    for (int nt = 0; nt < 8; ++nt) {
        const int v = nt * 8 + 2 * (lane & 3);
        #pragma unroll
        for (int half = 0; half < 2; ++half) {
            const int i = half ? r1 : r0;
            float o0 = oacc[nt][half * 2 + 0] * SCALE_ATT;
            float o1 = oacc[nt][half * 2 + 1] * SCALE_ATT;
            bf16 h0 = __float2bfloat16_rn(o0);
            bf16 h1 = __float2bfloat16_rn(o1);
            const size_t addr = ((size_t)(c * CH + i) * B_SZ + bb) * E_DIM + hh * 64 + v;
            *(uint32_t*)(g_ah + addr) = pk2(__bfloat162float(h0), __bfloat162float(h1));
            *(uint32_t*)(g_al + addr) = pk2(o0 - __bfloat162float(h0), o1 - __bfloat162float(h1));
        }
    }
}

// ---------------------------------------------------------------------------
extern "C" void kernel_launch(void* const* d_in, const int* in_sizes, int n_in,
                              void* d_out, int out_size)
{
    (void)in_sizes; (void)n_in; (void)out_size;
    const float* query = (const float*)d_in[0];
    const float* key_  = (const float*)d_in[1];
    const float* value = (const float*)d_in[2];
    const float* ipw   = (const float*)d_in[3];
    const float* ipb   = (const float*)d_in[4];
    const float* opw   = (const float*)d_in[5];
    const float* opb   = (const float*)d_in[6];
    float* out = (float*)d_out;

    cudaFuncSetAttribute(tc_inproj,
                         cudaFuncAttributeMaxDynamicSharedMemorySize, GEMM_SMEM);
    cudaFuncSetAttribute(tc_outproj,
                         cudaFuncAttributeMaxDynamicSharedMemorySize, GEMM_SMEM);
    cudaFuncSetAttribute(attn_mma_kernel,
                         cudaFuncAttributeMaxDynamicSharedMemorySize, ATT_SMEM);

    const int NX = TB * E_DIM;

    split_act<<<dim3(NX / 1024, 1, 3), 256>>>(query, key_, value);
    split_w<<<E_DIM * E_DIM / 256, 256>>>(ipw, opw);

    tc_inproj<<<dim3(E_DIM / 128, TB / 128, 3), 256, GEMM_SMEM>>>(ipb);

    kvchunk_kernel<<<dim3(NC, BHN), 256>>>();
    scan_kernel<<<BHN, 256>>>();
    attn_mma_kernel<<<dim3(NC, BHN), 256, ATT_SMEM>>>();

    tc_outproj<<<dim3(E_DIM / 128, TB / 128), 256, GEMM_SMEM>>>(opb, out);
}